// round 14
// baseline (speedup 1.0000x reference)
#include <cuda_runtime.h>
#include <cstdint>

// Resample (upfirdn2d, FIR=[1,3,3,1], up=2)
// x: (4,256,128,128) f32 -> out: (4,256,256,256) f32
//
//   out row 2m   = 1*x[m-1] + 3*x[m]
//   out row 2m+1 = 3*x[m]   + 1*x[m+1]
//   out col 2n   = 1*x[n-2] + 3*x[n-1]
//   out col 2n+1 = 3*x[n-1] + 1*x[n]
//   scale 1/16; out-of-range -> 0.
//
// R13: R12 (evict_last input loads) + evict_first on the TMA bulk store.
// Combined policy: streaming writes evict each other, leaving the 64 MB
// input L2-resident across graph replays -> removes residual DRAM reads.

#define H_IN  128
#define W_IN  128
#define W_OUT 256
#define BC    (4 * 256)
#define ROWS  4
#define WARPS 4

__device__ __forceinline__ uint32_t smem_u32(const void* p) {
    return (uint32_t)__cvta_generic_to_shared(p);
}

// Read-only load with L2 evict_last policy (cache_hint form).
__device__ __forceinline__ float2 ldg_el(const float2* p, uint64_t pol) {
    float2 v;
    asm volatile("ld.global.nc.L2::cache_hint.v2.f32 {%0, %1}, [%2], %3;"
                 : "=f"(v.x), "=f"(v.y) : "l"(p), "l"(pol));
    return v;
}

__device__ __forceinline__ float2 prev_lane_or_zero(float2 v, int lane) {
    float2 p;
    p.x = __shfl_up_sync(0xffffffffu, v.x, 1);
    p.y = __shfl_up_sync(0xffffffffu, v.y, 1);
    if (lane == 0) { p.x = 0.f; p.y = 0.f; }
    return p;
}

__device__ __forceinline__ float2 prev_lane_or_wrap(float2 v, float2 wrapSrc, int lane) {
    float2 p;
    p.x = __shfl_up_sync(0xffffffffu, v.x, 1);
    p.y = __shfl_up_sync(0xffffffffu, v.y, 1);
    const float wx = __shfl_sync(0xffffffffu, wrapSrc.x, 31);
    const float wy = __shfl_sync(0xffffffffu, wrapSrc.y, 31);
    if (lane == 0) { p.x = wx; p.y = wy; }
    return p;
}

__global__ __launch_bounds__(128) void upfir_up2_kernel(const float* __restrict__ x,
                                                        float* __restrict__ out) {
    __shared__ float4 stage[WARPS][ROWS * 128];         // 8 KB per warp (32 KB total)

    const int lane = threadIdx.x;                       // 0..31
    const int w    = threadIdx.y;                       // 0..3
    const int m0   = (blockIdx.y * WARPS + w) * ROWS;   // 0,4,...,124
    const int bc   = blockIdx.z;

    const float2* __restrict__ xin = (const float2*)(x + (size_t)bc * (H_IN * W_IN));
    float* __restrict__ o          = out + (size_t)bc * (2 * H_IN) * W_OUT;

    uint64_t polL;   // reads: keep resident
    asm volatile("createpolicy.fractional.L2::evict_last.b64 %0, 1.0;" : "=l"(polL));

    // Rows m0-1 .. m0+ROWS at indices 0..ROWS+1; two 64-col halves per row.
    float2 a[ROWS + 2], b[ROWS + 2];

#pragma unroll
    for (int i = 1; i <= ROWS; i++) {
        const float2* row = xin + (size_t)(m0 - 1 + i) * (W_IN / 2);
        a[i] = ldg_el(row + lane, polL);        // cols 2t, 2t+1
        b[i] = ldg_el(row + 32 + lane, polL);   // cols 64+2t, 65+2t
    }
    a[0] = make_float2(0.f, 0.f); b[0] = a[0];
    a[ROWS + 1] = a[0];           b[ROWS + 1] = a[0];
    if (m0 > 0) {
        const float2* row = xin + (size_t)(m0 - 1) * (W_IN / 2);
        a[0] = ldg_el(row + lane, polL);
        b[0] = ldg_el(row + 32 + lane, polL);
    }
    if (m0 + ROWS < H_IN) {
        const float2* row = xin + (size_t)(m0 + ROWS) * (W_IN / 2);
        a[ROWS + 1] = ldg_el(row + lane, polL);
        b[ROWS + 1] = ldg_el(row + 32 + lane, polL);
    }

    const float s = 1.f / 16.f;
    float4* st = &stage[w][0];
#pragma unroll
    for (int i = 0; i < ROWS; i++) {
        // Vertical FIR on own columns (row m = m0+i at index i+1).
        float2 eA, dA, eB, dB;
        eA.x = a[i].x + 3.f * a[i + 1].x;     eA.y = a[i].y + 3.f * a[i + 1].y;
        dA.x = 3.f * a[i + 1].x + a[i + 2].x; dA.y = 3.f * a[i + 1].y + a[i + 2].y;
        eB.x = b[i].x + 3.f * b[i + 1].x;     eB.y = b[i].y + 3.f * b[i + 1].y;
        dB.x = 3.f * b[i + 1].x + b[i + 2].x; dB.y = 3.f * b[i + 1].y + b[i + 2].y;

        const float2 peA = prev_lane_or_zero(eA, lane);
        const float2 pdA = prev_lane_or_zero(dA, lane);
        const float2 peB = prev_lane_or_wrap(eB, eA, lane);  // halfB lane0 <- halfA lane31
        const float2 pdB = prev_lane_or_wrap(dB, dA, lane);

        // Horizontal FIR -> 4 output cols per half per output row.
        float4 oEA = make_float4((peA.x + 3.f * peA.y) * s, (3.f * peA.y + eA.x) * s,
                                 (peA.y + 3.f * eA.x) * s,  (3.f * eA.x + eA.y) * s);
        float4 oDA = make_float4((pdA.x + 3.f * pdA.y) * s, (3.f * pdA.y + dA.x) * s,
                                 (pdA.y + 3.f * dA.x) * s,  (3.f * dA.x + dA.y) * s);
        float4 oEB = make_float4((peB.x + 3.f * peB.y) * s, (3.f * peB.y + eB.x) * s,
                                 (peB.y + 3.f * eB.x) * s,  (3.f * eB.x + eB.y) * s);
        float4 oDB = make_float4((pdB.x + 3.f * pdB.y) * s, (3.f * pdB.y + dB.x) * s,
                                 (pdB.y + 3.f * dB.x) * s,  (3.f * dB.x + dB.y) * s);

        // Stage rows 2(m0+i), 2(m0+i)+1 at float4 offsets 128*i .. 128*i+127.
        st[128 * i + lane]      = oEA;
        st[128 * i + 32 + lane] = oEB;
        st[128 * i + 64 + lane] = oDA;
        st[128 * i + 96 + lane] = oDB;
    }

    // One bulk store per warp: 8 KB contiguous, evict_first write policy.
    asm volatile("fence.proxy.async.shared::cta;" ::: "memory");
    __syncwarp();
    if (lane == 0) {
        void* gdst = (void*)(o + (size_t)(2 * m0) * W_OUT);
        uint64_t polF;
        asm volatile("createpolicy.fractional.L2::evict_first.b64 %0, 1.0;" : "=l"(polF));
        asm volatile("cp.async.bulk.global.shared::cta.bulk_group.L2::cache_hint"
                     " [%0], [%1], %2, %3;"
                     :: "l"(gdst), "r"(smem_u32(st)), "n"(ROWS * 2048), "l"(polF)
                     : "memory");
        asm volatile("cp.async.bulk.commit_group;" ::: "memory");
        asm volatile("cp.async.bulk.wait_group 0;" ::: "memory");
    }
    __syncwarp();
}

extern "C" void kernel_launch(void* const* d_in, const int* in_sizes, int n_in,
                              void* d_out, int out_size) {
    const float* x = (const float*)d_in[0];
    float* out = (float*)d_out;

    dim3 block(32, WARPS, 1);                   // 128 threads
    dim3 grid(1, H_IN / (WARPS * ROWS), BC);    // (1, 8, 1024)
    upfir_up2_kernel<<<grid, block>>>(x, out);
}

// round 15
// speedup vs baseline: 1.0052x; 1.0052x over previous
#include <cuda_runtime.h>
#include <cstdint>

// Resample (upfirdn2d, FIR=[1,3,3,1], up=2)
// x: (4,256,128,128) f32 -> out: (4,256,256,256) f32
//
//   out row 2m   = 1*x[m-1] + 3*x[m]
//   out row 2m+1 = 3*x[m]   + 1*x[m+1]
//   out col 2n   = 1*x[n-2] + 3*x[n-1]
//   out col 2n+1 = 3*x[n-1] + 1*x[n]
//   scale 1/16; out-of-range -> 0.
//
// R14 (lock-in): best measured config (R12) — warp spans row as two float2
// halves w/ shuffle halo, evict_last input loads, one plain 8 KB
// cp.async.bulk per warp — with wait_group.read (read-completion suffices
// for SMEM lifetime; writes flush at kernel boundary).
// Established roofline: 256 MB write stream at ~5.46 TB/s mixed-rate.

#define H_IN  128
#define W_IN  128
#define W_OUT 256
#define BC    (4 * 256)
#define ROWS  4
#define WARPS 4

__device__ __forceinline__ uint32_t smem_u32(const void* p) {
    return (uint32_t)__cvta_generic_to_shared(p);
}

// Read-only load with L2 evict_last policy (cache_hint form).
__device__ __forceinline__ float2 ldg_el(const float2* p, uint64_t pol) {
    float2 v;
    asm volatile("ld.global.nc.L2::cache_hint.v2.f32 {%0, %1}, [%2], %3;"
                 : "=f"(v.x), "=f"(v.y) : "l"(p), "l"(pol));
    return v;
}

__device__ __forceinline__ float2 prev_lane_or_zero(float2 v, int lane) {
    float2 p;
    p.x = __shfl_up_sync(0xffffffffu, v.x, 1);
    p.y = __shfl_up_sync(0xffffffffu, v.y, 1);
    if (lane == 0) { p.x = 0.f; p.y = 0.f; }
    return p;
}

__device__ __forceinline__ float2 prev_lane_or_wrap(float2 v, float2 wrapSrc, int lane) {
    float2 p;
    p.x = __shfl_up_sync(0xffffffffu, v.x, 1);
    p.y = __shfl_up_sync(0xffffffffu, v.y, 1);
    const float wx = __shfl_sync(0xffffffffu, wrapSrc.x, 31);
    const float wy = __shfl_sync(0xffffffffu, wrapSrc.y, 31);
    if (lane == 0) { p.x = wx; p.y = wy; }
    return p;
}

__global__ __launch_bounds__(128) void upfir_up2_kernel(const float* __restrict__ x,
                                                        float* __restrict__ out) {
    __shared__ float4 stage[WARPS][ROWS * 128];         // 8 KB per warp (32 KB total)

    const int lane = threadIdx.x;                       // 0..31
    const int w    = threadIdx.y;                       // 0..3
    const int m0   = (blockIdx.y * WARPS + w) * ROWS;   // 0,4,...,124
    const int bc   = blockIdx.z;

    const float2* __restrict__ xin = (const float2*)(x + (size_t)bc * (H_IN * W_IN));
    float* __restrict__ o          = out + (size_t)bc * (2 * H_IN) * W_OUT;

    uint64_t polL;   // reads: keep resident
    asm volatile("createpolicy.fractional.L2::evict_last.b64 %0, 1.0;" : "=l"(polL));

    // Rows m0-1 .. m0+ROWS at indices 0..ROWS+1; two 64-col halves per row.
    float2 a[ROWS + 2], b[ROWS + 2];

#pragma unroll
    for (int i = 1; i <= ROWS; i++) {
        const float2* row = xin + (size_t)(m0 - 1 + i) * (W_IN / 2);
        a[i] = ldg_el(row + lane, polL);        // cols 2t, 2t+1
        b[i] = ldg_el(row + 32 + lane, polL);   // cols 64+2t, 65+2t
    }
    a[0] = make_float2(0.f, 0.f); b[0] = a[0];
    a[ROWS + 1] = a[0];           b[ROWS + 1] = a[0];
    if (m0 > 0) {
        const float2* row = xin + (size_t)(m0 - 1) * (W_IN / 2);
        a[0] = ldg_el(row + lane, polL);
        b[0] = ldg_el(row + 32 + lane, polL);
    }
    if (m0 + ROWS < H_IN) {
        const float2* row = xin + (size_t)(m0 + ROWS) * (W_IN / 2);
        a[ROWS + 1] = ldg_el(row + lane, polL);
        b[ROWS + 1] = ldg_el(row + 32 + lane, polL);
    }

    const float s = 1.f / 16.f;
    float4* st = &stage[w][0];
#pragma unroll
    for (int i = 0; i < ROWS; i++) {
        // Vertical FIR on own columns (row m = m0+i at index i+1).
        float2 eA, dA, eB, dB;
        eA.x = a[i].x + 3.f * a[i + 1].x;     eA.y = a[i].y + 3.f * a[i + 1].y;
        dA.x = 3.f * a[i + 1].x + a[i + 2].x; dA.y = 3.f * a[i + 1].y + a[i + 2].y;
        eB.x = b[i].x + 3.f * b[i + 1].x;     eB.y = b[i].y + 3.f * b[i + 1].y;
        dB.x = 3.f * b[i + 1].x + b[i + 2].x; dB.y = 3.f * b[i + 1].y + b[i + 2].y;

        const float2 peA = prev_lane_or_zero(eA, lane);
        const float2 pdA = prev_lane_or_zero(dA, lane);
        const float2 peB = prev_lane_or_wrap(eB, eA, lane);  // halfB lane0 <- halfA lane31
        const float2 pdB = prev_lane_or_wrap(dB, dA, lane);

        // Horizontal FIR -> 4 output cols per half per output row.
        float4 oEA = make_float4((peA.x + 3.f * peA.y) * s, (3.f * peA.y + eA.x) * s,
                                 (peA.y + 3.f * eA.x) * s,  (3.f * eA.x + eA.y) * s);
        float4 oDA = make_float4((pdA.x + 3.f * pdA.y) * s, (3.f * pdA.y + dA.x) * s,
                                 (pdA.y + 3.f * dA.x) * s,  (3.f * dA.x + dA.y) * s);
        float4 oEB = make_float4((peB.x + 3.f * peB.y) * s, (3.f * peB.y + eB.x) * s,
                                 (peB.y + 3.f * eB.x) * s,  (3.f * eB.x + eB.y) * s);
        float4 oDB = make_float4((pdB.x + 3.f * pdB.y) * s, (3.f * pdB.y + dB.x) * s,
                                 (pdB.y + 3.f * dB.x) * s,  (3.f * dB.x + dB.y) * s);

        // Stage rows 2(m0+i), 2(m0+i)+1 at float4 offsets 128*i .. 128*i+127.
        st[128 * i + lane]      = oEA;
        st[128 * i + 32 + lane] = oEB;
        st[128 * i + 64 + lane] = oDA;
        st[128 * i + 96 + lane] = oDB;
    }

    // One bulk store per warp: 8 KB contiguous (output rows 2m0 .. 2m0+7).
    // wait_group.read: SMEM lifetime needs only read-completion; the writes
    // themselves are flushed at kernel boundary.
    asm volatile("fence.proxy.async.shared::cta;" ::: "memory");
    __syncwarp();
    if (lane == 0) {
        void* gdst = (void*)(o + (size_t)(2 * m0) * W_OUT);
        asm volatile("cp.async.bulk.global.shared::cta.bulk_group [%0], [%1], %2;"
                     :: "l"(gdst), "r"(smem_u32(st)), "n"(ROWS * 2048) : "memory");
        asm volatile("cp.async.bulk.commit_group;" ::: "memory");
        asm volatile("cp.async.bulk.wait_group.read 0;" ::: "memory");
    }
    __syncwarp();
}

extern "C" void kernel_launch(void* const* d_in, const int* in_sizes, int n_in,
                              void* d_out, int out_size) {
    const float* x = (const float*)d_in[0];
    float* out = (float*)d_out;

    dim3 block(32, WARPS, 1);                   // 128 threads
    dim3 grid(1, H_IN / (WARPS * ROWS), BC);    // (1, 8, 1024)
    upfir_up2_kernel<<<grid, block>>>(x, out);
}